// round 14
// baseline (speedup 1.0000x reference)
#include <cuda_runtime.h>
#include <cuda_fp16.h>
#include <math_constants.h>
#include <cstdint>

// Problem constants (fixed by the dataset)
#define CC    64
#define NB    2048
#define NT    20
#define NN    (NB * NT)          // 40960 nodes
#define NE    1310720            // edges
#define EDGE_GRID 592            // persistent blocks (4 per SM)
#define NWARPS (EDGE_GRID * 8)   // 4736 warps, dst nodes strided across them

// k_edge smem: per-warp A tiles + shared B (fp16)
#define ASTR    144              // A row: 64 fp16 (128B) + 16B pad
#define AWARP   (16 * ASTR)      // 2304 per warp
#define BOFF    (8 * AWARP)      // 18432
#define BSTRIDE 144              // B row: 64 fp16 + pad
#define DYNSZ   (BOFF + 64 * BSTRIDE)   // 27648

// k_scannode smem: W1 transposed [k][c] float2 (stride 65) + x transposed [k][n]
#define SN_W1OFF  0                       // float2 W1kc[64][65] = 33280B
#define SN_XTOFF  33280                   // float xs_t[64][68] = 17408B
#define SN_DYNSZ  (33280 + 17408)         // 50688

// -------- persistent device scratch (zero-initialized at load) --------
__device__ __align__(16) __half g_uh[NN * CC];   // fp16(x @ (W1a-W1b)^T + b1)
__device__ __align__(16) __half g_vh[NN * CC];   // fp16(x @ W1b^T)
__device__ int g_deg[NN];        // zero-init; re-zeroed by k_scannode each run
__device__ int g_rowptr[NN + 1];
__device__ int g_rank[NE];       // rank of edge within its dst bucket
__device__ int g_ss[NE];         // edge src sorted by dst (CSR)

// per-block edge_index dtype detection (int64 layout has odd 32-bit words all 0)
__device__ __forceinline__ int detect_is64(const void* ei, int* s_flag, int tid) {
    if (tid < 32) {
        int v = ((const int*)ei)[2 * tid + 1];
        unsigned m = __ballot_sync(0xFFFFFFFFu, v != 0);
        if (tid == 0) *s_flag = (m == 0u);
    }
    __syncthreads();
    return *s_flag;
}

// load 4 consecutive indices (16B/32B vectorized)
__device__ __forceinline__ void load_idx4(const void* ei, long long pos, int is64, int* d) {
    if (is64) {
        const uint4* p = (const uint4*)((const long long*)ei + pos);
        uint4 a = p[0], b = p[1];
        d[0] = (int)a.x; d[1] = (int)a.z; d[2] = (int)b.x; d[3] = (int)b.z;
    } else {
        uint4 a = *(const uint4*)((const int*)ei + pos);
        d[0] = (int)a.x; d[1] = (int)a.y; d[2] = (int)a.z; d[3] = (int)a.w;
    }
}

// ---------------- launch 0: degree histogram + per-edge rank (8 edges/thread) ----------------
__global__ void __launch_bounds__(256) k_hist(const void* __restrict__ ei) {
    __shared__ int s_flag;
    int tid = threadIdx.x;
    int is64 = detect_is64(ei, &s_flag, tid);
    int e = (blockIdx.x * 256 + tid) * 8;
    int d[8];
    load_idx4(ei, (long long)NE + e, is64, d);
    load_idx4(ei, (long long)NE + e + 4, is64, d + 4);
    #pragma unroll
    for (int j = 0; j < 8; j++)
        if ((unsigned)d[j] < NN) g_rank[e + j] = atomicAdd(&g_deg[d[j]], 1);
}

// ---------------- launch 1: block 0 = scan (+re-zero deg), others = node GEMM ----------------
__global__ void __launch_bounds__(1024) k_scannode(
    const float* __restrict__ x, const float* __restrict__ W1,
    const float* __restrict__ b1)
{
    extern __shared__ __align__(16) char snsm[];
    int tid = threadIdx.x;

    if (blockIdx.x == 0) {
        int* sums = (int*)snsm;
        int base = tid * 40;
        int s = 0;
        for (int i = 0; i < 40; i++) s += g_deg[base + i];
        sums[tid] = s;
        __syncthreads();
        for (int off = 1; off < 1024; off <<= 1) {
            int a = sums[tid];
            int b = (tid >= off) ? sums[tid - off] : 0;
            __syncthreads();
            sums[tid] = a + b;
            __syncthreads();
        }
        int run = (tid > 0) ? sums[tid - 1] : 0;
        for (int i = 0; i < 40; i++) {
            g_rowptr[base + i] = run;
            run += g_deg[base + i];
            g_deg[base + i] = 0;        // ready for next replay
        }
        if (tid == 1023) g_rowptr[NN] = run;
        return;
    }

    // W1kc[k][c] = (W1[c][k], W1[c][64+k]) float2, row stride 65 (2-way STS once,
    // conflict-free lane-contiguous LDS in the hot loop)
    float2* W1kc = (float2*)(snsm + SN_W1OFF);
    float* xs_t  = (float*)(snsm + SN_XTOFF);    // x transposed [k][n], stride 68
    for (int i = tid; i < 64 * 64; i += 1024) {
        int k = i & 63, c = i >> 6;              // coalesced W1 reads (k contiguous)
        W1kc[k * 65 + c] = make_float2(W1[c * 128 + k], W1[c * 128 + 64 + k]);
    }
    int node0 = (blockIdx.x - 1) * 64;
    for (int i = tid; i < 64 * 64; i += 1024) {
        int n = i >> 6, k = i & 63;
        xs_t[k * 68 + n] = x[node0 * 64 + i];
    }
    __syncthreads();

    int c = tid & 63;
    int g = tid >> 6;
    float ua[4] = {0.f, 0.f, 0.f, 0.f};
    float vb[4] = {0.f, 0.f, 0.f, 0.f};
    #pragma unroll 8
    for (int k = 0; k < 64; k++) {
        float2 w = W1kc[k * 65 + c];             // lane-contiguous: 2 wf, no conflicts
        float4 xv = *(const float4*)(xs_t + k * 68 + g * 4);   // warp-broadcast: 1 wf
        ua[0] = fmaf(xv.x, w.x, ua[0]); vb[0] = fmaf(xv.x, w.y, vb[0]);
        ua[1] = fmaf(xv.y, w.x, ua[1]); vb[1] = fmaf(xv.y, w.y, vb[1]);
        ua[2] = fmaf(xv.z, w.x, ua[2]); vb[2] = fmaf(xv.z, w.y, vb[2]);
        ua[3] = fmaf(xv.w, w.x, ua[3]); vb[3] = fmaf(xv.w, w.y, vb[3]);
    }
    float bc = b1[c];
    #pragma unroll
    for (int j = 0; j < 4; j++) {
        int n = node0 + g * 4 + j;
        g_uh[n * 64 + c] = __float2half_rn(ua[j] - vb[j] + bc);
        g_vh[n * 64 + c] = __float2half_rn(vb[j]);
    }
}

// ---------------- launch 2: scatter src into CSR order (no atomics, 8/thread) ----------------
__global__ void __launch_bounds__(256) k_scatter(const void* __restrict__ ei) {
    __shared__ int s_flag;
    int tid = threadIdx.x;
    int is64 = detect_is64(ei, &s_flag, tid);
    int e = (blockIdx.x * 256 + tid) * 8;
    int d[8], s[8];
    load_idx4(ei, (long long)NE + e, is64, d);
    load_idx4(ei, (long long)NE + e + 4, is64, d + 4);
    load_idx4(ei, (long long)e, is64, s);
    load_idx4(ei, (long long)e + 4, is64, s + 4);
    uint4 rka = *(const uint4*)(g_rank + e);
    uint4 rkb = *(const uint4*)(g_rank + e + 4);
    unsigned r[8] = {rka.x, rka.y, rka.z, rka.w, rkb.x, rkb.y, rkb.z, rkb.w};
    #pragma unroll
    for (int j = 0; j < 8; j++)
        if ((unsigned)d[j] < NN && (unsigned)s[j] < NN)
            g_ss[g_rowptr[d[j]] + (int)r[j]] = s[j];
}

#define LDSM4(r0, r1, r2, r3, addr) \
    asm volatile("ldmatrix.sync.aligned.m8n8.x4.shared.b16 {%0,%1,%2,%3}, [%4];" \
        : "=r"(r0), "=r"(r1), "=r"(r2), "=r"(r3) : "r"(addr))

#define MMA16816(acc, a0, a1, a2, a3, b0, b1) \
    asm volatile("mma.sync.aligned.m16n8k16.row.col.f32.f16.f16.f32 " \
        "{%0,%1,%2,%3}, {%4,%5,%6,%7}, {%8,%9}, {%0,%1,%2,%3};" \
        : "+f"((acc)[0]), "+f"((acc)[1]), "+f"((acc)[2]), "+f"((acc)[3]) \
        : "r"(a0), "r"(a1), "r"(a2), "r"(a3), "r"(b0), "r"(b1))

// ---------------- launch 3: warp-per-dst HMMA edge GEMM, direct output ----------------
// Each warp owns whole dst nodes (strided): chunks of 16 edges -> MMA -> register fmax
// merge -> one shuffle reduction + coalesced STG per dst (bias+residual+relu fused).
// A-fragments preloaded to registers (np-outer MMA); next chunk's src index load is
// software-pipelined across the MMA section.
__global__ void __launch_bounds__(256, 4) k_edge(
    const float* __restrict__ W2, const float* __restrict__ x,
    const float* __restrict__ b2, float* __restrict__ out)
{
    extern __shared__ __align__(16) char sm[];
    uint32_t sb = (uint32_t)__cvta_generic_to_shared(sm);
    int tid = threadIdx.x;
    int wid = tid >> 5;
    int lane = tid & 31;

    // ---- B = fp16(W2), [n][k] rows (col-major kxn for mma .col) ----
    for (int i = tid; i < 64 * 64; i += 256) {
        int n = i >> 6, k = i & 63;
        *(__half*)(sm + BOFF + n * BSTRIDE + k * 2) = __float2half_rn(W2[i]);
    }
    __syncthreads();
    uint32_t bBase = sb + BOFF + (uint32_t)((lane & 7) + ((lane >> 4) << 3)) * BSTRIDE
                   + (((lane >> 3) & 1) << 4);

    char* aw = sm + wid * AWARP;                      // this warp's A tile
    uint32_t aLane = sb + (uint32_t)(wid * AWARP)
                   + (uint32_t)(lane & 15) * ASTR + (((uint32_t)lane >> 4) << 4);
    int rq = lane >> 2;          // fragment row (0..7; +8 pair)
    int q2 = (lane & 3) * 2;     // fragment col pair base
    int pr = lane >> 3;          // prep row-within-group (0..3)
    int pc = lane & 7;           // prep 16B block within row (0..7)

    const __half2 c001 = __half2half2(__float2half_rn(0.01f));
    float2 bpair = *(const float2*)(b2 + rq * 8 + q2);   // this lane's output cols
    int wgid = blockIdx.x * 8 + wid;

    for (int node = wgid; node < NN; node += NWARPS) {
        int beg = g_rowptr[node];
        int end = g_rowptr[node + 1];
        float2 xv = *(const float2*)(x + node * 64 + rq * 8 + q2);
        float* op = out + node * 64 + rq * 8 + q2;
        if (beg == end) {   // empty dst: agg = 0
            *(float2*)op = make_float2(fmaxf(xv.x, 0.0f), fmaxf(xv.y, 0.0f));
            continue;
        }
        uint4 uu = *(const uint4*)(g_uh + node * 64 + pc * 8);   // u row, per-dst

        float macc[8][2];
        #pragma unroll
        for (int ni = 0; ni < 8; ni++) { macc[ni][0] = -CUDART_INF_F; macc[ni][1] = -CUDART_INF_F; }

        // software-pipelined src index (duplicate a real edge on tail: max-safe)
        int sidx = beg + (lane & 15);
        if (sidx >= end) sidx = end - 1;
        int src = g_ss[sidx];

        for (int cb = beg; cb < end; cb += 16) {
            // prefetch next chunk's src (hidden behind prep + MMA)
            int nidx = cb + 16 + (lane & 15);
            if (nidx >= end) nidx = end - 1;
            int src_next = g_ss[nidx];

            // ---- prep: v gather, h = lrelu(u+v) in half2, STS.128 ----
            #pragma unroll
            for (int it = 0; it < 4; it++) {
                int r = 4 * it + pr;
                int sn = __shfl_sync(0xFFFFFFFFu, src, r);
                uint4 vv = *(const uint4*)(g_vh + sn * 64 + pc * 8);
                uint4 hh;
                {
                    __half2 h;
                    h = __hadd2(*(__half2*)&uu.x, *(__half2*)&vv.x);
                    h = __hmax2(h, __hmul2(h, c001)); hh.x = *(unsigned*)&h;
                    h = __hadd2(*(__half2*)&uu.y, *(__half2*)&vv.y);
                    h = __hmax2(h, __hmul2(h, c001)); hh.y = *(unsigned*)&h;
                    h = __hadd2(*(__half2*)&uu.z, *(__half2*)&vv.z);
                    h = __hmax2(h, __hmul2(h, c001)); hh.z = *(unsigned*)&h;
                    h = __hadd2(*(__half2*)&uu.w, *(__half2*)&vv.w);
                    h = __hmax2(h, __hmul2(h, c001)); hh.w = *(unsigned*)&h;
                }
                *(uint4*)(aw + r * ASTR + pc * 16) = hh;
            }
            __syncwarp();

            // ---- preload all A fragments (frees the tile early) ----
            uint32_t Af[4][4];
            #pragma unroll
            for (int ks = 0; ks < 4; ks++)
                LDSM4(Af[ks][0], Af[ks][1], Af[ks][2], Af[ks][3],
                      aLane + (uint32_t)(ks * 32));
            __syncwarp();   // A tile free: next chunk's STS may proceed after MMA issue

            // ---- np-outer MMA: transient 8-reg acc per 16-col group ----
            #pragma unroll
            for (int np = 0; np < 4; np++) {
                float acc0[4] = {0.f, 0.f, 0.f, 0.f};
                float acc1[4] = {0.f, 0.f, 0.f, 0.f};
                #pragma unroll
                for (int ks = 0; ks < 4; ks++) {
                    uint32_t b0, b1, b2r, b3;
                    LDSM4(b0, b1, b2r, b3,
                          bBase + (uint32_t)(ks * 32) + (uint32_t)(np * 16) * BSTRIDE);
                    MMA16816(acc0, Af[ks][0], Af[ks][1], Af[ks][2], Af[ks][3], b0, b1);
                    MMA16816(acc1, Af[ks][0], Af[ks][1], Af[ks][2], Af[ks][3], b2r, b3);
                }
                macc[2 * np][0]     = fmaxf(macc[2 * np][0],     fmaxf(acc0[0], acc0[2]));
                macc[2 * np][1]     = fmaxf(macc[2 * np][1],     fmaxf(acc0[1], acc0[3]));
                macc[2 * np + 1][0] = fmaxf(macc[2 * np + 1][0], fmaxf(acc1[0], acc1[2]));
                macc[2 * np + 1][1] = fmaxf(macc[2 * np + 1][1], fmaxf(acc1[1], acc1[3]));
            }
            src = src_next;
        }

        // ---- one shuffle reduction per dst: max over the 8 row-groups ----
        float r0 = 0.0f, r1 = 0.0f;
        #pragma unroll
        for (int ni = 0; ni < 8; ni++) {
            float m0 = macc[ni][0], m1 = macc[ni][1];
            #pragma unroll
            for (int off = 4; off <= 16; off <<= 1) {
                m0 = fmaxf(m0, __shfl_xor_sync(0xFFFFFFFFu, m0, off));
                m1 = fmaxf(m1, __shfl_xor_sync(0xFFFFFFFFu, m1, off));
            }
            if (rq == ni) { r0 = m0; r1 = m1; }
        }
        // ---- fused epilogue: +b2, residual, relu, direct store ----
        *(float2*)op = make_float2(fmaxf(r0 + bpair.x + xv.x, 0.0f),
                                   fmaxf(r1 + bpair.y + xv.y, 0.0f));
    }
}

// ---------------- launch ----------------
extern "C" void kernel_launch(void* const* d_in, const int* in_sizes, int n_in,
                              void* d_out, int out_size) {
    const float* x  = (const float*)d_in[0];
    const void*  ei = d_in[1];
    const float* W1 = (const float*)d_in[2];
    const float* b1 = (const float*)d_in[3];
    const float* W2 = (const float*)d_in[4];
    const float* b2 = (const float*)d_in[5];
    float* out = (float*)d_out;

    cudaFuncSetAttribute(k_scannode, cudaFuncAttributeMaxDynamicSharedMemorySize, SN_DYNSZ);
    cudaFuncSetAttribute(k_edge, cudaFuncAttributeMaxDynamicSharedMemorySize, DYNSZ);

    k_hist    <<<NE / 2048, 256>>>(ei);
    k_scannode<<<NN / 64 + 1, 1024, SN_DYNSZ>>>(x, W1, b1);
    k_scatter <<<NE / 2048, 256>>>(ei);
    k_edge    <<<EDGE_GRID, 256, DYNSZ>>>(W2, x, b2, out);
}

// round 15
// speedup vs baseline: 1.4158x; 1.4158x over previous
#include <cuda_runtime.h>
#include <cuda_fp16.h>
#include <math_constants.h>
#include <cstdint>

// Problem constants (fixed by the dataset)
#define CC    64
#define NB    2048
#define NT    20
#define NN    (NB * NT)          // 40960 nodes
#define NE    1310720            // edges
#define MAXG  1184               // max persistent blocks supported

// edge-phase smem layout
#define ASTR    144              // A row: 64 fp16 (128B) + 16B pad
#define AWARP   (16 * ASTR)      // 2304 per warp
#define BOFF    (8 * AWARP)      // 18432
#define BSTRIDE 144              // B row: 64 fp16 + pad
// node-phase smem layout
#define SN_W1OFF  0              // float2 W1kc[64][65] = 33280B
#define SN_XTOFF  33280          // float xs_t[64][20] = 5120B
#define DYNSZ     38400          // max over phases

#define NTILE_NODE (NN / 16)     // 2560 node tiles of 16
#define NHIST      (NE / 2048)   // 640 hist/scatter iterations of 2048 edges

// -------- persistent device scratch (zero-initialized at load) --------
__device__ __align__(16) __half g_uh[NN * CC];   // fp16(x @ (W1a-W1b)^T + b1)
__device__ __align__(16) __half g_vh[NN * CC];   // fp16(x @ W1b^T)
__device__ int g_deg[NN];        // zero-init; re-zeroed in scan phase each run
__device__ int g_rowptr[NN + 1];
__device__ int g_rank[NE];       // rank of edge within its dst bucket
__device__ int g_ss[NE];         // edge src sorted by dst (CSR)
__device__ unsigned g_bsum[MAXG];
__device__ unsigned g_bbase[MAXG];
__device__ unsigned g_cnt;                 // barrier arrival counter (returns to 0)
__device__ volatile unsigned g_gen;        // barrier generation (monotonic)

// ---------------- device-wide barrier (all blocks co-resident) ----------------
__device__ __forceinline__ void gsync(int G) {
    __syncthreads();
    if (threadIdx.x == 0) {
        __threadfence();
        unsigned g = g_gen;
        if (atomicAdd(&g_cnt, 1u) == (unsigned)G - 1u) {
            g_cnt = 0;
            __threadfence();
            g_gen = g + 1;
        } else {
            while (g_gen == g) { }
            __threadfence();
        }
    }
    __syncthreads();
}

// edge_index dtype detection (int64 layout has odd 32-bit words all 0)
__device__ __forceinline__ int detect_is64(const void* ei, int* s_flag, int tid) {
    if (tid < 32) {
        int v = ((const int*)ei)[2 * tid + 1];
        unsigned m = __ballot_sync(0xFFFFFFFFu, v != 0);
        if (tid == 0) *s_flag = (m == 0u);
    }
    __syncthreads();
    return *s_flag;
}

__device__ __forceinline__ void load_idx4(const void* ei, long long pos, int is64, int* d) {
    if (is64) {
        const uint4* p = (const uint4*)((const long long*)ei + pos);
        uint4 a = p[0], b = p[1];
        d[0] = (int)a.x; d[1] = (int)a.z; d[2] = (int)b.x; d[3] = (int)b.z;
    } else {
        uint4 a = *(const uint4*)((const int*)ei + pos);
        d[0] = (int)a.x; d[1] = (int)a.y; d[2] = (int)a.z; d[3] = (int)a.w;
    }
}

// ---- phase-A workers ----
__device__ __forceinline__ void do_hist(const void* ei, int is64, int it0, int it1,
                                        int stride, int tid) {
    for (int it = it0; it < it1; it += stride) {
        int e = (it * 256 + tid) * 8;
        int d[8];
        load_idx4(ei, (long long)NE + e, is64, d);
        load_idx4(ei, (long long)NE + e + 4, is64, d + 4);
        #pragma unroll
        for (int j = 0; j < 8; j++)
            if ((unsigned)d[j] < NN) g_rank[e + j] = atomicAdd(&g_deg[d[j]], 1);
    }
}

__device__ __forceinline__ void do_gemm(const float* x, const float* b1, char* sm,
                                        int t0, int t1, int stride, int tid) {
    float2* W1kc = (float2*)(sm + SN_W1OFF);
    float*  xs_t = (float*)(sm + SN_XTOFF);
    int c = tid & 63;
    int g = tid >> 6;
    float bc = b1[c];
    for (int t = t0; t < t1; t += stride) {
        int node0 = t * 16;
        __syncthreads();   // xs_t readers from previous tile done
        for (int i = tid; i < 16 * 64; i += 256) {
            int n = i >> 6, k = i & 63;
            xs_t[k * 20 + n] = x[node0 * 64 + i];
        }
        __syncthreads();
        float ua[4] = {0.f, 0.f, 0.f, 0.f};
        float vb[4] = {0.f, 0.f, 0.f, 0.f};
        #pragma unroll 8
        for (int k = 0; k < 64; k++) {
            float2 w = W1kc[k * 65 + c];
            float4 xv = *(const float4*)(xs_t + k * 20 + g * 4);
            ua[0] = fmaf(xv.x, w.x, ua[0]); vb[0] = fmaf(xv.x, w.y, vb[0]);
            ua[1] = fmaf(xv.y, w.x, ua[1]); vb[1] = fmaf(xv.y, w.y, vb[1]);
            ua[2] = fmaf(xv.z, w.x, ua[2]); vb[2] = fmaf(xv.z, w.y, vb[2]);
            ua[3] = fmaf(xv.w, w.x, ua[3]); vb[3] = fmaf(xv.w, w.y, vb[3]);
        }
        #pragma unroll
        for (int j = 0; j < 4; j++) {
            int n = node0 + g * 4 + j;
            g_uh[n * 64 + c] = __float2half_rn(ua[j] - vb[j] + bc);
            g_vh[n * 64 + c] = __float2half_rn(vb[j]);
        }
    }
}

#define LDSM4(r0, r1, r2, r3, addr) \
    asm volatile("ldmatrix.sync.aligned.m8n8.x4.shared.b16 {%0,%1,%2,%3}, [%4];" \
        : "=r"(r0), "=r"(r1), "=r"(r2), "=r"(r3) : "r"(addr))

#define MMA16816(acc, a0, a1, a2, a3, b0, b1) \
    asm volatile("mma.sync.aligned.m16n8k16.row.col.f32.f16.f16.f32 " \
        "{%0,%1,%2,%3}, {%4,%5,%6,%7}, {%8,%9}, {%0,%1,%2,%3};" \
        : "+f"((acc)[0]), "+f"((acc)[1]), "+f"((acc)[2]), "+f"((acc)[3]) \
        : "r"(a0), "r"(a1), "r"(a2), "r"(a3), "r"(b0), "r"(b1))

// ================= fused persistent kernel =================
__global__ void __launch_bounds__(256, 4) k_all(
    const float* __restrict__ x, const void* __restrict__ ei,
    const float* __restrict__ W1, const float* __restrict__ b1,
    const float* __restrict__ W2, const float* __restrict__ b2,
    float* __restrict__ out)
{
    extern __shared__ __align__(16) char sm[];
    __shared__ int s_flag;
    int tid = threadIdx.x;
    int G = gridDim.x;
    int is64 = detect_is64(ei, &s_flag, tid);

    // ---------- Phase A: node GEMM + hist, split by block parity for overlap ----------
    {
        // load W1 transposed (needed by every block's gemm half)
        float2* W1kc = (float2*)(sm + SN_W1OFF);
        for (int i = tid; i < 64 * 64; i += 256) {
            int k = i & 63, c = i >> 6;
            W1kc[k * 65 + c] = make_float2(W1[c * 128 + k], W1[c * 128 + 64 + k]);
        }
        __syncthreads();
        int half = G >> 1;                 // G is even (SM count 148 x occ)
        int sub = blockIdx.x >> 1;
        if ((blockIdx.x & 1) == 0) {
            do_hist(ei, is64, sub, NHIST / 2, half, tid);
            do_gemm(x, b1, sm, NTILE_NODE / 2 + sub, NTILE_NODE, half, tid);
        } else {
            do_gemm(x, b1, sm, sub, NTILE_NODE / 2, half, tid);
            do_hist(ei, is64, NHIST / 2 + sub, NHIST, half, tid);
        }
    }
    gsync(G);

    // ---------- Phase B1: per-block partial sums of g_deg ----------
    int CH = (NN + G - 1) / G;
    {
        int start = blockIdx.x * CH;
        int end = min(start + CH, NN);
        unsigned s = 0;
        for (int i = start + tid; i < end; i += 256) s += (unsigned)g_deg[i];
        unsigned* red = (unsigned*)sm;
        red[tid] = s;
        __syncthreads();
        for (int off = 128; off; off >>= 1) {
            if (tid < off) red[tid] += red[tid + off];
            __syncthreads();
        }
        if (tid == 0) g_bsum[blockIdx.x] = red[0];
    }
    gsync(G);

    // ---------- Phase B2: block 0 warp 0 scans the G partials ----------
    if (blockIdx.x == 0 && tid < 32) {
        int lane = tid;
        int per = (G + 31) >> 5;
        int s0 = lane * per;
        unsigned s = 0;
        for (int i = 0; i < per; i++) {
            int idx = s0 + i;
            if (idx < G) s += g_bsum[idx];
        }
        unsigned acc = s;
        #pragma unroll
        for (int off = 1; off < 32; off <<= 1) {
            unsigned t = __shfl_up_sync(0xFFFFFFFFu, acc, off);
            if (lane >= off) acc += t;
        }
        unsigned run = acc - s;            // exclusive
        for (int i = 0; i < per; i++) {
            int idx = s0 + i;
            if (idx < G) { g_bbase[idx] = run; run += g_bsum[idx]; }
        }
        if (lane == 31) g_rowptr[NN] = (int)run;   // grand total
    }
    gsync(G);

    // ---------- Phase B3: per-block local exclusive scan + re-zero deg ----------
    if (tid < 32) {
        int lane = tid;
        int start = blockIdx.x * CH;
        int end = min(start + CH, NN);
        int len = end - start;
        if (len > 0) {
            int per = (len + 31) >> 5;
            int ls = start + lane * per;
            int le = min(ls + per, end);
            unsigned s = 0;
            for (int i = ls; i < le; i++) s += (unsigned)g_deg[i];
            unsigned acc = s;
            #pragma unroll
            for (int off = 1; off < 32; off <<= 1) {
                unsigned t = __shfl_up_sync(0xFFFFFFFFu, acc, off);
                if (lane >= off) acc += t;
            }
            unsigned run = g_bbase[blockIdx.x] + (acc - s);
            for (int i = ls; i < le; i++) {
                g_rowptr[i] = (int)run;
                run += (unsigned)g_deg[i];
                g_deg[i] = 0;              // ready for next replay
            }
        }
    }
    gsync(G);

    // ---------- Phase C: scatter src into CSR order (no atomics) ----------
    for (int it = blockIdx.x; it < NHIST; it += G) {
        int e = (it * 256 + tid) * 8;
        int d[8], s[8];
        load_idx4(ei, (long long)NE + e, is64, d);
        load_idx4(ei, (long long)NE + e + 4, is64, d + 4);
        load_idx4(ei, (long long)e, is64, s);
        load_idx4(ei, (long long)e + 4, is64, s + 4);
        uint4 rka = *(const uint4*)(g_rank + e);
        uint4 rkb = *(const uint4*)(g_rank + e + 4);
        unsigned r[8] = {rka.x, rka.y, rka.z, rka.w, rkb.x, rkb.y, rkb.z, rkb.w};
        #pragma unroll
        for (int j = 0; j < 8; j++)
            if ((unsigned)d[j] < NN && (unsigned)s[j] < NN)
                g_ss[g_rowptr[d[j]] + (int)r[j]] = s[j];
    }
    gsync(G);

    // ---------- Phase D: warp-per-dst HMMA edge GEMM, direct output ----------
    {
        uint32_t sb = (uint32_t)__cvta_generic_to_shared(sm);
        int wid = tid >> 5;
        int lane = tid & 31;

        // B = fp16(W2), [n][k] rows
        for (int i = tid; i < 64 * 64; i += 256) {
            int n = i >> 6, k = i & 63;
            *(__half*)(sm + BOFF + n * BSTRIDE + k * 2) = __float2half_rn(W2[i]);
        }
        __syncthreads();
        uint32_t bBase = sb + BOFF + (uint32_t)((lane & 7) + ((lane >> 4) << 3)) * BSTRIDE
                       + (((lane >> 3) & 1) << 4);
        char* aw = sm + wid * AWARP;
        uint32_t aLane = sb + (uint32_t)(wid * AWARP)
                       + (uint32_t)(lane & 15) * ASTR + (((uint32_t)lane >> 4) << 4);
        int rq = lane >> 2;
        int q2 = (lane & 3) * 2;
        int pr = lane >> 3;
        int pc = lane & 7;
        const __half2 c001 = __half2half2(__float2half_rn(0.01f));
        float2 bpair = *(const float2*)(b2 + rq * 8 + q2);
        int nwarps = G * 8;
        int wgid = blockIdx.x * 8 + wid;

        for (int node = wgid; node < NN; node += nwarps) {
            int beg = g_rowptr[node];
            int end = g_rowptr[node + 1];
            float2 xv = *(const float2*)(x + node * 64 + rq * 8 + q2);
            float* op = out + node * 64 + rq * 8 + q2;
            if (beg == end) {
                *(float2*)op = make_float2(fmaxf(xv.x, 0.0f), fmaxf(xv.y, 0.0f));
                continue;
            }
            uint4 uu = *(const uint4*)(g_uh + node * 64 + pc * 8);

            float macc[8][2];
            #pragma unroll
            for (int ni = 0; ni < 8; ni++) { macc[ni][0] = -CUDART_INF_F; macc[ni][1] = -CUDART_INF_F; }

            int sidx = beg + (lane & 15);
            if (sidx >= end) sidx = end - 1;
            int src = g_ss[sidx];

            for (int cb = beg; cb < end; cb += 16) {
                int nidx = cb + 16 + (lane & 15);
                if (nidx >= end) nidx = end - 1;
                int src_next = g_ss[nidx];

                #pragma unroll
                for (int it = 0; it < 4; it++) {
                    int r = 4 * it + pr;
                    int sn = __shfl_sync(0xFFFFFFFFu, src, r);
                    uint4 vv = *(const uint4*)(g_vh + sn * 64 + pc * 8);
                    uint4 hh;
                    {
                        __half2 h;
                        h = __hadd2(*(__half2*)&uu.x, *(__half2*)&vv.x);
                        h = __hmax2(h, __hmul2(h, c001)); hh.x = *(unsigned*)&h;
                        h = __hadd2(*(__half2*)&uu.y, *(__half2*)&vv.y);
                        h = __hmax2(h, __hmul2(h, c001)); hh.y = *(unsigned*)&h;
                        h = __hadd2(*(__half2*)&uu.z, *(__half2*)&vv.z);
                        h = __hmax2(h, __hmul2(h, c001)); hh.z = *(unsigned*)&h;
                        h = __hadd2(*(__half2*)&uu.w, *(__half2*)&vv.w);
                        h = __hmax2(h, __hmul2(h, c001)); hh.w = *(unsigned*)&h;
                    }
                    *(uint4*)(aw + r * ASTR + pc * 16) = hh;
                }
                __syncwarp();

                uint32_t Af[4][4];
                #pragma unroll
                for (int ks = 0; ks < 4; ks++)
                    LDSM4(Af[ks][0], Af[ks][1], Af[ks][2], Af[ks][3],
                          aLane + (uint32_t)(ks * 32));
                __syncwarp();

                #pragma unroll
                for (int np = 0; np < 4; np++) {
                    float acc0[4] = {0.f, 0.f, 0.f, 0.f};
                    float acc1[4] = {0.f, 0.f, 0.f, 0.f};
                    #pragma unroll
                    for (int ks = 0; ks < 4; ks++) {
                        uint32_t b0, b1r, b2r, b3;
                        LDSM4(b0, b1r, b2r, b3,
                              bBase + (uint32_t)(ks * 32) + (uint32_t)(np * 16) * BSTRIDE);
                        MMA16816(acc0, Af[ks][0], Af[ks][1], Af[ks][2], Af[ks][3], b0, b1r);
                        MMA16816(acc1, Af[ks][0], Af[ks][1], Af[ks][2], Af[ks][3], b2r, b3);
                    }
                    macc[2 * np][0]     = fmaxf(macc[2 * np][0],     fmaxf(acc0[0], acc0[2]));
                    macc[2 * np][1]     = fmaxf(macc[2 * np][1],     fmaxf(acc0[1], acc0[3]));
                    macc[2 * np + 1][0] = fmaxf(macc[2 * np + 1][0], fmaxf(acc1[0], acc1[2]));
                    macc[2 * np + 1][1] = fmaxf(macc[2 * np + 1][1], fmaxf(acc1[1], acc1[3]));
                }
                src = src_next;
            }

            float r0 = 0.0f, r1 = 0.0f;
            #pragma unroll
            for (int ni = 0; ni < 8; ni++) {
                float m0 = macc[ni][0], m1 = macc[ni][1];
                #pragma unroll
                for (int off = 4; off <= 16; off <<= 1) {
                    m0 = fmaxf(m0, __shfl_xor_sync(0xFFFFFFFFu, m0, off));
                    m1 = fmaxf(m1, __shfl_xor_sync(0xFFFFFFFFu, m1, off));
                }
                if (rq == ni) { r0 = m0; r1 = m1; }
            }
            *(float2*)op = make_float2(fmaxf(r0 + bpair.x + xv.x, 0.0f),
                                       fmaxf(r1 + bpair.y + xv.y, 0.0f));
        }
    }
}

// ---------------- launch ----------------
extern "C" void kernel_launch(void* const* d_in, const int* in_sizes, int n_in,
                              void* d_out, int out_size) {
    const float* x  = (const float*)d_in[0];
    const void*  ei = d_in[1];
    const float* W1 = (const float*)d_in[2];
    const float* b1 = (const float*)d_in[3];
    const float* W2 = (const float*)d_in[4];
    const float* b2 = (const float*)d_in[5];
    float* out = (float*)d_out;

    cudaFuncSetAttribute(k_all, cudaFuncAttributeMaxDynamicSharedMemorySize, DYNSZ);

    int nb = 0;
    cudaOccupancyMaxActiveBlocksPerMultiprocessor(&nb, k_all, 256, DYNSZ);
    int sms = 0;
    cudaDeviceGetAttribute(&sms, cudaDevAttrMultiProcessorCount, 0);
    int G = nb * sms;
    if (G > MAXG) G = MAXG;
    if (G < 2) G = 2;
    G &= ~1;            // even, for the parity work split

    k_all<<<G, 256, DYNSZ>>>(x, ei, W1, b1, W2, b2, out);
}

// round 16
// speedup vs baseline: 1.5188x; 1.0728x over previous
#include <cuda_runtime.h>
#include <cuda_fp16.h>
#include <math_constants.h>
#include <cstdint>

// Problem constants (fixed by the dataset)
#define CC    64
#define NB    2048
#define NT    20
#define NN    (NB * NT)          // 40960 nodes
#define NE    1310720            // edges
#define MAXG  1184               // max persistent blocks supported

// shared smem layout (A tiles + B tile), reused by node and edge phases
#define ASTR    144              // A row: 64 fp16 (128B) + 16B pad
#define AWARP   (16 * ASTR)      // 2304 per warp
#define BOFF    (8 * AWARP)      // 18432
#define BSTRIDE 144              // B row: 64 fp16 + pad
#define DYNSZ   38400            // >= BOFF + 128*BSTRIDE = 36864

#define NTILE128 (NN / 128)      // 320 node tiles of 128
#define NHIST    (NE / 2048)     // 640 hist/scatter iterations of 2048 edges

// -------- persistent device scratch (zero-initialized at load) --------
__device__ __align__(16) __half g_uh[NN * CC];   // fp16(x @ (W1a-W1b)^T + b1)
__device__ __align__(16) __half g_vh[NN * CC];   // fp16(x @ W1b^T)
__device__ int g_deg[NN];        // zero-init; re-zeroed in scan phase each run
__device__ int g_rowptr[NN + 1];
__device__ int g_rank[NE];       // rank of edge within its dst bucket
__device__ int g_ss[NE];         // edge src sorted by dst (CSR)
__device__ unsigned g_bsum[MAXG];
__device__ unsigned g_bbase[MAXG];
__device__ unsigned g_cnt;                 // barrier arrival counter (returns to 0)
__device__ volatile unsigned g_gen;        // barrier generation (monotonic)

// ---------------- device-wide barrier (all blocks co-resident) ----------------
__device__ __forceinline__ void gsync(int G) {
    __syncthreads();
    if (threadIdx.x == 0) {
        __threadfence();
        unsigned g = g_gen;
        if (atomicAdd(&g_cnt, 1u) == (unsigned)G - 1u) {
            g_cnt = 0;
            __threadfence();
            g_gen = g + 1;
        } else {
            while (g_gen == g) { }
            __threadfence();
        }
    }
    __syncthreads();
}

// edge_index dtype detection (int64 layout has odd 32-bit words all 0)
__device__ __forceinline__ int detect_is64(const void* ei, int* s_flag, int tid) {
    if (tid < 32) {
        int v = ((const int*)ei)[2 * tid + 1];
        unsigned m = __ballot_sync(0xFFFFFFFFu, v != 0);
        if (tid == 0) *s_flag = (m == 0u);
    }
    __syncthreads();
    return *s_flag;
}

__device__ __forceinline__ void load_idx4(const void* ei, long long pos, int is64, int* d) {
    if (is64) {
        const uint4* p = (const uint4*)((const long long*)ei + pos);
        uint4 a = p[0], b = p[1];
        d[0] = (int)a.x; d[1] = (int)a.z; d[2] = (int)b.x; d[3] = (int)b.z;
    } else {
        uint4 a = *(const uint4*)((const int*)ei + pos);
        d[0] = (int)a.x; d[1] = (int)a.y; d[2] = (int)a.z; d[3] = (int)a.w;
    }
}

#define LDSM4(r0, r1, r2, r3, addr) \
    asm volatile("ldmatrix.sync.aligned.m8n8.x4.shared.b16 {%0,%1,%2,%3}, [%4];" \
        : "=r"(r0), "=r"(r1), "=r"(r2), "=r"(r3) : "r"(addr))

#define MMA16816(acc, a0, a1, a2, a3, b0, b1) \
    asm volatile("mma.sync.aligned.m16n8k16.row.col.f32.f16.f16.f32 " \
        "{%0,%1,%2,%3}, {%4,%5,%6,%7}, {%8,%9}, {%0,%1,%2,%3};" \
        : "+f"((acc)[0]), "+f"((acc)[1]), "+f"((acc)[2]), "+f"((acc)[3]) \
        : "r"(a0), "r"(a1), "r"(a2), "r"(a3), "r"(b0), "r"(b1))

// ---- phase-A workers ----
__device__ __forceinline__ void do_hist(const void* ei, int is64, int it0, int it1,
                                        int stride, int tid) {
    for (int it = it0; it < it1; it += stride) {
        int e = (it * 256 + tid) * 8;
        int d[8];
        load_idx4(ei, (long long)NE + e, is64, d);
        load_idx4(ei, (long long)NE + e + 4, is64, d + 4);
        #pragma unroll
        for (int j = 0; j < 8; j++)
            if ((unsigned)d[j] < NN) g_rank[e + j] = atomicAdd(&g_deg[d[j]], 1);
    }
}

// node GEMM on tensor cores: u = x@(W1a-W1b)^T + b1, v = x@W1b^T (fp16 A/B, fp32 acc)
// B tile (built per block before call): rows 0-63 = W1a-W1b [n][k], rows 64-127 = W1b
__device__ __forceinline__ void do_node_mma(
    const float* __restrict__ x, const float* __restrict__ b1,
    char* sm, uint32_t sb, int t0, int t1, int stride, int tid)
{
    int wid = tid >> 5;
    int lane = tid & 31;
    char* aw = sm + wid * AWARP;
    uint32_t aLane = sb + (uint32_t)(wid * AWARP)
                   + (uint32_t)(lane & 15) * ASTR + (((uint32_t)lane >> 4) << 4);
    uint32_t bBase = sb + BOFF + (uint32_t)((lane & 7) + ((lane >> 4) << 3)) * BSTRIDE
                   + (((lane >> 3) & 1) << 4);
    int rq = lane >> 2;
    int q2 = (lane & 3) * 2;
    int pr = lane >> 3;
    int pc = lane & 7;

    for (int t = t0; t < t1; t += stride) {
        int n0 = t * 128 + wid * 16;
        // ---- prep: x rows (contiguous nodes) -> fp16 A tile ----
        #pragma unroll
        for (int it = 0; it < 4; it++) {
            int r = 4 * it + pr;
            const float4* xr = (const float4*)(x + (n0 + r) * 64);
            #pragma unroll
            for (int h = 0; h < 2; h++) {
                float4 a = xr[h * 8 + pc];
                __half2 p0 = __floats2half2_rn(a.x, a.y);
                __half2 p1 = __floats2half2_rn(a.z, a.w);
                *(uint2*)(aw + r * ASTR + h * 64 + pc * 8) =
                    make_uint2(*(unsigned*)&p0, *(unsigned*)&p1);
            }
        }
        __syncwarp();
        uint32_t Af[4][4];
        #pragma unroll
        for (int ks = 0; ks < 4; ks++)
            LDSM4(Af[ks][0], Af[ks][1], Af[ks][2], Af[ks][3],
                  aLane + (uint32_t)(ks * 32));
        __syncwarp();

        // ---- np 0..3: u (with b1), np 4..7: v ----
        #pragma unroll
        for (int np = 0; np < 8; np++) {
            float acc0[4] = {0.f, 0.f, 0.f, 0.f};
            float acc1[4] = {0.f, 0.f, 0.f, 0.f};
            #pragma unroll
            for (int ks = 0; ks < 4; ks++) {
                uint32_t b0, b1r, b2r, b3;
                LDSM4(b0, b1r, b2r, b3,
                      bBase + (uint32_t)(ks * 32) + (uint32_t)(np * 16) * BSTRIDE);
                MMA16816(acc0, Af[ks][0], Af[ks][1], Af[ks][2], Af[ks][3], b0, b1r);
                MMA16816(acc1, Af[ks][0], Af[ks][1], Af[ks][2], Af[ks][3], b2r, b3);
            }
            int colb = (np & 3) * 16 + q2;
            __half* dst;
            float bb0 = 0.f, bb1 = 0.f, bc0 = 0.f, bc1 = 0.f;
            if (np < 4) {
                dst = g_uh;
                bb0 = b1[colb];     bb1 = b1[colb + 1];
                bc0 = b1[colb + 8]; bc1 = b1[colb + 9];
            } else {
                dst = g_vh;
            }
            int row0 = n0 + rq, row1 = n0 + rq + 8;
            __half2 h;
            h = __floats2half2_rn(acc0[0] + bb0, acc0[1] + bb1);
            *(__half2*)(dst + row0 * 64 + colb) = h;
            h = __floats2half2_rn(acc0[2] + bb0, acc0[3] + bb1);
            *(__half2*)(dst + row1 * 64 + colb) = h;
            h = __floats2half2_rn(acc1[0] + bc0, acc1[1] + bc1);
            *(__half2*)(dst + row0 * 64 + colb + 8) = h;
            h = __floats2half2_rn(acc1[2] + bc0, acc1[3] + bc1);
            *(__half2*)(dst + row1 * 64 + colb + 8) = h;
        }
    }
}

// ================= fused persistent kernel =================
__global__ void __launch_bounds__(256, 4) k_all(
    const float* __restrict__ x, const void* __restrict__ ei,
    const float* __restrict__ W1, const float* __restrict__ b1,
    const float* __restrict__ W2, const float* __restrict__ b2,
    float* __restrict__ out)
{
    extern __shared__ __align__(16) char sm[];
    __shared__ int s_flag;
    int tid = threadIdx.x;
    int G = gridDim.x;
    uint32_t sb = (uint32_t)__cvta_generic_to_shared(sm);
    int is64 = detect_is64(ei, &s_flag, tid);

    // ---------- Phase A: node MMA GEMM + hist, split by block parity ----------
    {
        // build B tile: rows 0-63 = W1a-W1b, rows 64-127 = W1b (fp16 [n][k])
        for (int i = tid; i < 128 * 64; i += 256) {
            int n = i >> 6, k = i & 63;
            float val = (n < 64) ? (W1[n * 128 + k] - W1[n * 128 + 64 + k])
                                 : W1[(n - 64) * 128 + 64 + k];
            *(__half*)(sm + BOFF + n * BSTRIDE + k * 2) = __float2half_rn(val);
        }
        __syncthreads();
        int half = G >> 1;
        int sub = blockIdx.x >> 1;
        if ((blockIdx.x & 1) == 0) {
            do_hist(ei, is64, sub, NHIST / 2, half, tid);
            do_node_mma(x, b1, sm, sb, NTILE128 / 2 + sub, NTILE128, half, tid);
        } else {
            do_node_mma(x, b1, sm, sb, sub, NTILE128 / 2, half, tid);
            do_hist(ei, is64, NHIST / 2 + sub, NHIST, half, tid);
        }
    }
    gsync(G);

    // ---------- Phase B1: per-block partial sums of g_deg ----------
    int CH = (NN + G - 1) / G;
    {
        int start = blockIdx.x * CH;
        int end = min(start + CH, NN);
        unsigned s = 0;
        for (int i = start + tid; i < end; i += 256) s += (unsigned)g_deg[i];
        unsigned* red = (unsigned*)sm;
        red[tid] = s;
        __syncthreads();
        for (int off = 128; off; off >>= 1) {
            if (tid < off) red[tid] += red[tid + off];
            __syncthreads();
        }
        if (tid == 0) g_bsum[blockIdx.x] = red[0];
    }
    gsync(G);

    // ---------- Phase B2: block 0 warp 0 scans the G partials ----------
    if (blockIdx.x == 0 && tid < 32) {
        int lane = tid;
        int per = (G + 31) >> 5;
        int s0 = lane * per;
        unsigned s = 0;
        for (int i = 0; i < per; i++) {
            int idx = s0 + i;
            if (idx < G) s += g_bsum[idx];
        }
        unsigned acc = s;
        #pragma unroll
        for (int off = 1; off < 32; off <<= 1) {
            unsigned t = __shfl_up_sync(0xFFFFFFFFu, acc, off);
            if (lane >= off) acc += t;
        }
        unsigned run = acc - s;            // exclusive
        for (int i = 0; i < per; i++) {
            int idx = s0 + i;
            if (idx < G) { g_bbase[idx] = run; run += g_bsum[idx]; }
        }
        if (lane == 31) g_rowptr[NN] = (int)run;
    }
    gsync(G);

    // ---------- Phase B3: per-block local exclusive scan + re-zero deg ----------
    if (tid < 32) {
        int lane = tid;
        int start = blockIdx.x * CH;
        int end = min(start + CH, NN);
        int len = end - start;
        if (len > 0) {
            int per = (len + 31) >> 5;
            int ls = start + lane * per;
            int le = min(ls + per, end);
            unsigned s = 0;
            for (int i = ls; i < le; i++) s += (unsigned)g_deg[i];
            unsigned acc = s;
            #pragma unroll
            for (int off = 1; off < 32; off <<= 1) {
                unsigned t = __shfl_up_sync(0xFFFFFFFFu, acc, off);
                if (lane >= off) acc += t;
            }
            unsigned run = g_bbase[blockIdx.x] + (acc - s);
            for (int i = ls; i < le; i++) {
                g_rowptr[i] = (int)run;
                run += (unsigned)g_deg[i];
                g_deg[i] = 0;
            }
        }
    }
    gsync(G);

    // ---------- Phase C: scatter + build W2 fp16 B tile (smem free here) ----------
    for (int i = tid; i < 64 * 64; i += 256) {
        int n = i >> 6, k = i & 63;
        *(__half*)(sm + BOFF + n * BSTRIDE + k * 2) = __float2half_rn(W2[i]);
    }
    for (int it = blockIdx.x; it < NHIST; it += G) {
        int e = (it * 256 + tid) * 8;
        int d[8], s[8];
        load_idx4(ei, (long long)NE + e, is64, d);
        load_idx4(ei, (long long)NE + e + 4, is64, d + 4);
        load_idx4(ei, (long long)e, is64, s);
        load_idx4(ei, (long long)e + 4, is64, s + 4);
        uint4 rka = *(const uint4*)(g_rank + e);
        uint4 rkb = *(const uint4*)(g_rank + e + 4);
        unsigned r[8] = {rka.x, rka.y, rka.z, rka.w, rkb.x, rkb.y, rkb.z, rkb.w};
        #pragma unroll
        for (int j = 0; j < 8; j++)
            if ((unsigned)d[j] < NN && (unsigned)s[j] < NN)
                g_ss[g_rowptr[d[j]] + (int)r[j]] = s[j];
    }
    gsync(G);

    // ---------- Phase D: warp-per-dst HMMA edge GEMM, direct output ----------
    {
        int wid = tid >> 5;
        int lane = tid & 31;
        uint32_t bBase = sb + BOFF + (uint32_t)((lane & 7) + ((lane >> 4) << 3)) * BSTRIDE
                       + (((lane >> 3) & 1) << 4);
        char* aw = sm + wid * AWARP;
        uint32_t aLane = sb + (uint32_t)(wid * AWARP)
                       + (uint32_t)(lane & 15) * ASTR + (((uint32_t)lane >> 4) << 4);
        int rq = lane >> 2;
        int q2 = (lane & 3) * 2;
        int pr = lane >> 3;
        int pc = lane & 7;
        const __half2 c001 = __half2half2(__float2half_rn(0.01f));
        float2 bpair = *(const float2*)(b2 + rq * 8 + q2);
        int nwarps = G * 8;
        int wgid = blockIdx.x * 8 + wid;

        for (int node = wgid; node < NN; node += nwarps) {
            int beg = g_rowptr[node];
            int end = g_rowptr[node + 1];
            float2 xv = *(const float2*)(x + node * 64 + rq * 8 + q2);
            float* op = out + node * 64 + rq * 8 + q2;
            if (beg == end) {
                *(float2*)op = make_float2(fmaxf(xv.x, 0.0f), fmaxf(xv.y, 0.0f));
                continue;
            }
            uint4 uu = *(const uint4*)(g_uh + node * 64 + pc * 8);

            float macc[8][2];
            #pragma unroll
            for (int ni = 0; ni < 8; ni++) { macc[ni][0] = -CUDART_INF_F; macc[ni][1] = -CUDART_INF_F; }

            int sidx = beg + (lane & 15);
            if (sidx >= end) sidx = end - 1;
            int src = g_ss[sidx];

            for (int cb = beg; cb < end; cb += 16) {
                int nidx = cb + 16 + (lane & 15);
                if (nidx >= end) nidx = end - 1;
                int src_next = g_ss[nidx];

                // ---- prep: 2-wide batched v gather, h = lrelu(u+v), STS.128 ----
                #pragma unroll
                for (int ip = 0; ip < 2; ip++) {
                    int r0 = 8 * ip + pr, r1 = 8 * ip + 4 + pr;
                    int sn0 = __shfl_sync(0xFFFFFFFFu, src, r0);
                    int sn1 = __shfl_sync(0xFFFFFFFFu, src, r1);
                    uint4 vv0 = *(const uint4*)(g_vh + sn0 * 64 + pc * 8);
                    uint4 vv1 = *(const uint4*)(g_vh + sn1 * 64 + pc * 8);
                    uint4 hh;
                    __half2 h;
                    h = __hadd2(*(__half2*)&uu.x, *(__half2*)&vv0.x);
                    h = __hmax2(h, __hmul2(h, c001)); hh.x = *(unsigned*)&h;
                    h = __hadd2(*(__half2*)&uu.y, *(__half2*)&vv0.y);
                    h = __hmax2(h, __hmul2(h, c001)); hh.y = *(unsigned*)&h;
                    h = __hadd2(*(__half2*)&uu.z, *(__half2*)&vv0.z);
                    h = __hmax2(h, __hmul2(h, c001)); hh.z = *(unsigned*)&h;
                    h = __hadd2(*(__half2*)&uu.w, *(__half2*)&vv0.w);
                    h = __hmax2(h, __hmul2(h, c001)); hh.w = *(unsigned*)&h;
                    *(uint4*)(aw + r0 * ASTR + pc * 16) = hh;
                    h = __hadd2(*(__half2*)&uu.x, *(__half2*)&vv1.x);
                    h = __hmax2(h, __hmul2(h, c001)); hh.x = *(unsigned*)&h;
                    h = __hadd2(*(__half2*)&uu.y, *(__half2*)&vv1.y);
                    h = __hmax2(h, __hmul2(h, c001)); hh.y = *(unsigned*)&h;
                    h = __hadd2(*(__half2*)&uu.z, *(__half2*)&vv1.z);
                    h = __hmax2(h, __hmul2(h, c001)); hh.z = *(unsigned*)&h;
                    h = __hadd2(*(__half2*)&uu.w, *(__half2*)&vv1.w);
                    h = __hmax2(h, __hmul2(h, c001)); hh.w = *(unsigned*)&h;
                    *(uint4*)(aw + r1 * ASTR + pc * 16) = hh;
                }
                __syncwarp();

                uint32_t Af[4][4];
                #pragma unroll
                for (int ks = 0; ks < 4; ks++)
                    LDSM4(Af[ks][0], Af[ks][1], Af[ks][2], Af[ks][3],
                          aLane + (uint32_t)(ks * 32));
                __syncwarp();

                #pragma unroll
                for (int np = 0; np < 4; np++) {
                    float acc0[4] = {0.f, 0.f, 0.f, 0.f};
                    float acc1[4] = {0.f, 0.f, 0.f, 0.f};
                    #pragma unroll
                    for (int ks = 0; ks < 4; ks++) {
                        uint32_t b0, b1r, b2r, b3;
                        LDSM4(b0, b1r, b2r, b3,
                              bBase + (uint32_t)(ks * 32) + (uint32_t)(np * 16) * BSTRIDE);
                        MMA16816(acc0, Af[ks][0], Af[ks][1], Af[ks][2], Af[ks][3], b0, b1r);
                        MMA16816(acc1, Af[ks][0], Af[ks][1], Af[ks][2], Af[ks][3], b2r, b3);
                    }
                    macc[2 * np][0]     = fmaxf(macc[2 * np][0],     fmaxf(acc0[0], acc0[2]));
                    macc[2 * np][1]     = fmaxf(macc[2 * np][1],     fmaxf(acc0[1], acc0[3]));
                    macc[2 * np + 1][0] = fmaxf(macc[2 * np + 1][0], fmaxf(acc1[0], acc1[2]));
                    macc[2 * np + 1][1] = fmaxf(macc[2 * np + 1][1], fmaxf(acc1[1], acc1[3]));
                }
                src = src_next;
            }

            float r0 = 0.0f, r1 = 0.0f;
            #pragma unroll
            for (int ni = 0; ni < 8; ni++) {
                float m0 = macc[ni][0], m1 = macc[ni][1];
                #pragma unroll
                for (int off = 4; off <= 16; off <<= 1) {
                    m0 = fmaxf(m0, __shfl_xor_sync(0xFFFFFFFFu, m0, off));
                    m1 = fmaxf(m1, __shfl_xor_sync(0xFFFFFFFFu, m1, off));
                }
                if (rq == ni) { r0 = m0; r1 = m1; }
            }
            *(float2*)op = make_float2(fmaxf(r0 + bpair.x + xv.x, 0.0f),
                                       fmaxf(r1 + bpair.y + xv.y, 0.0f));
        }
    }
}

// ---------------- launch ----------------
extern "C" void kernel_launch(void* const* d_in, const int* in_sizes, int n_in,
                              void* d_out, int out_size) {
    const float* x  = (const float*)d_in[0];
    const void*  ei = d_in[1];
    const float* W1 = (const float*)d_in[2];
    const float* b1 = (const float*)d_in[3];
    const float* W2 = (const float*)d_in[4];
    const float* b2 = (const float*)d_in[5];
    float* out = (float*)d_out;

    cudaFuncSetAttribute(k_all, cudaFuncAttributeMaxDynamicSharedMemorySize, DYNSZ);

    int nb = 0;
    cudaOccupancyMaxActiveBlocksPerMultiprocessor(&nb, k_all, 256, DYNSZ);
    int sms = 0;
    cudaDeviceGetAttribute(&sms, cudaDevAttrMultiProcessorCount, 0);
    int G = nb * sms;
    if (G > MAXG) G = MAXG;
    if (G < 2) G = 2;
    G &= ~1;            // even, for the parity work split

    k_all<<<G, 256, DYNSZ>>>(x, ei, W1, b1, W2, b2, out);
}